// round 4
// baseline (speedup 1.0000x reference)
#include <cuda_runtime.h>
#include <cuda_bf16.h>
#include <cstdint>

// Problem constants
#define TT 1024
#define BB 128
#define HH 100
#define IN_ 100
#define GG 400   // 4*H

// ---------------- scratch (device globals: no allocs allowed) ----------------
__device__ float g_xT[(size_t)TT * BB * IN_];          // (T,B,IN)      52.4 MB
__device__ float g_gx[(size_t)2 * TT * BB * GG];       // (dir,T,B,4H) 419.4 MB
__device__ float g_mid[(size_t)TT * BB * 2 * HH];      // (T,B,2H)     104.9 MB

// ---------------- f32x2 helpers ----------------
__device__ __forceinline__ unsigned long long pk2(float a, float b) {
    unsigned long long r;
    asm("mov.b64 %0, {%1,%2};" : "=l"(r) : "f"(a), "f"(b));
    return r;
}
__device__ __forceinline__ unsigned long long fma2(unsigned long long a,
                                                   unsigned long long b,
                                                   unsigned long long c) {
    unsigned long long d;
    asm("fma.rn.f32x2 %0, %1, %2, %3;" : "=l"(d) : "l"(a), "l"(b), "l"(c));
    return d;
}
__device__ __forceinline__ float hsum2(unsigned long long a, unsigned long long b) {
    unsigned long long s;
    asm("add.rn.f32x2 %0, %1, %2;" : "=l"(s) : "l"(a), "l"(b));
    float lo, hi;
    asm("mov.b64 {%0,%1}, %2;" : "=f"(lo), "=f"(hi) : "l"(s));
    return lo + hi;
}

// ---------------- fast activations (MUFU-based, rel err ~1e-6) ----------------
__device__ __forceinline__ float fexp2(float x) {
    float r; asm("ex2.approx.f32 %0, %1;" : "=f"(r) : "f"(x)); return r;
}
__device__ __forceinline__ float frcpa(float x) {
    float r; asm("rcp.approx.f32 %0, %1;" : "=f"(r) : "f"(x)); return r;
}
__device__ __forceinline__ float fsig(float x) {
    return frcpa(1.0f + fexp2(-1.4426950408889634f * x));
}
__device__ __forceinline__ float ftanh(float x) {
    return fmaf(2.0f, frcpa(1.0f + fexp2(-2.8853900817779268f * x)), -1.0f);
}

// ---------------- kernel 1: transpose x (B,IN,T) -> xT (T,B,IN) ----------------
__global__ void transpose_x(const float* __restrict__ x, float* __restrict__ xT) {
    __shared__ float tile[32][33];
    int b  = blockIdx.z;
    int k0 = blockIdx.y * 32;
    int t0 = blockIdx.x * 32;
    int tx = threadIdx.x, ty = threadIdx.y;   // 32 x 8
    #pragma unroll
    for (int i = ty; i < 32; i += 8) {
        int k = k0 + i;
        tile[i][tx] = (k < IN_) ? x[((size_t)b * IN_ + k) * TT + (t0 + tx)] : 0.0f;
    }
    __syncthreads();
    #pragma unroll
    for (int i = ty; i < 32; i += 8) {
        int t = t0 + i, k = k0 + tx;
        if (k < IN_)
            xT[((size_t)t * BB + b) * IN_ + k] = tile[tx][i];
    }
}

// ---------------- kernel 2: gate GEMM, K-split register-stationary --------------
// (unchanged from R2 — 800 threads, no spills)
template<int KF>
__global__ __launch_bounds__(800, 1) void gate_gemm2(
    const float* __restrict__ src, int srcStride,
    const float* __restrict__ Wih, int wStride,
    const float* __restrict__ bias,
    float* __restrict__ out)
{
    constexpr int NBLK = (KF == 100) ? 13 : 25;
    constexpr int ROWF = (KF == 100) ? 104 : 200;
    constexpr int BPR  = ROWF / 4;
    constexpr int NLD  = 16 * BPR;

    const int M   = TT * BB;
    const int CPD = 74;
    const int RPC = 1776;
    int dir   = blockIdx.x / CPD;
    int chunk = blockIdx.x % CPD;
    int row0  = chunk * RPC;
    int rowHi = min(row0 + RPC, M);

    int tid = threadIdx.x;
    int wp  = tid >> 5, ln = tid & 31;
    int j   = wp * 16 + (ln & 15);
    int kh  = ln >> 4;

    __shared__ float stage[16][ROWF];

    unsigned long long w[2 * NBLK];
    {
        const float* wrow = Wih + (size_t)(dir * GG + j) * wStride;
        #pragma unroll
        for (int i = 0; i < NBLK; i++) {
            int col = (KF == 100) ? (8 * i + 4 * kh) : (kh * 100 + 4 * i);
            float4 t = make_float4(0.f, 0.f, 0.f, 0.f);
            if (col < KF) t = *(const float4*)(wrow + col);
            w[2 * i]     = pk2(t.x, t.y);
            w[2 * i + 1] = pk2(t.z, t.w);
        }
    }
    float bj = bias[dir * GG + j];

    int r_ld = tid / BPR;
    int c_ld = (tid % BPR) * 4;
    float4 v = make_float4(0.f, 0.f, 0.f, 0.f);
    if (tid < NLD && c_ld < KF) {
        int rr = min(row0 + r_ld, M - 1);
        v = *(const float4*)(src + (size_t)rr * srcStride + c_ld);
    }

    int ntiles = (rowHi - row0 + 15) / 16;
    for (int tI = 0; tI < ntiles; tI++) {
        __syncthreads();
        if (tid < NLD) *(float4*)&stage[r_ld][c_ld] = v;
        __syncthreads();
        if (tid < NLD && c_ld < KF && tI + 1 < ntiles) {
            int rr = min(row0 + (tI + 1) * 16 + r_ld, M - 1);
            v = *(const float4*)(src + (size_t)rr * srcStride + c_ld);
        }
        int rlim = min(16, rowHi - row0 - tI * 16);
        for (int r = 0; r < rlim; r++) {
            unsigned long long a0 = 0, a1 = 0;
            #pragma unroll
            for (int i = 0; i < NBLK; i++) {
                int off = (KF == 100) ? (8 * i + 4 * kh) : (kh * 100 + 4 * i);
                ulonglong2 hv = *(const ulonglong2*)&stage[r][off];
                a0 = fma2(w[2 * i],     hv.x, a0);
                a1 = fma2(w[2 * i + 1], hv.y, a1);
            }
            float g = hsum2(a0, a1);
            g += __shfl_xor_sync(0xffffffffu, g, 16);
            if ((ln & 16) == 0) {
                size_t orow = (size_t)(row0 + tI * 16 + r);
                out[((size_t)dir * M + orow) * GG + j] = g + bj;
            }
        }
    }
}

// ---------------- kernel 3: staggered-row recurrence scan ----------------------
// 128 CTAs: dir = blk>>6, pair = blk&63, rows (2*pair, 2*pair+1).
// 800 threads: tid<400 -> gate j=tid, K-half 0 (h cols 0..51);
//              tid>=400 -> gate j=tid-400, K-half 1 (h cols 52..99, padded to 103).
// 2T+1 intervals: interval s runs GEMV of row (s&1) at t=s>>1 CONCURRENTLY with
// the epilogue of the other row at t=(s-1)>>1. One __syncthreads per interval.
// K-half partials combined by the epilogue (no shfl). gx (incl. bias) is added by
// the epilogue from a register prefetch carried 2 intervals deep.
__global__ __launch_bounds__(800, 1) void lstm_scan3(
    const float* __restrict__ gx,     // (2,T,B,4H)
    const float* __restrict__ Whh,    // (2,4H,H)
    float* __restrict__ out,          // (T,B,outStride)
    int outStride)
{
    int dir  = blockIdx.x >> 6;
    int pair = blockIdx.x & 63;
    int b0r  = pair * 2;

    int tid = threadIdx.x;
    int kh  = (tid >= 400) ? 1 : 0;
    int j   = tid - 400 * kh;

    __shared__ float sh_h[2][104];       // [row][h], cols 100..103 stay 0
    __shared__ float sg[2][2][400];      // [row][khalf][gate] partial sums

    // stationary W_hh: 13 float4-blocks at h-cols kh*52 + 4i (block 12 of kh1 = 0)
    unsigned long long w[26];
    {
        const float* wrow = Whh + (size_t)(dir * GG + j) * HH;
        #pragma unroll
        for (int i = 0; i < 13; i++) {
            int col = kh * 52 + 4 * i;
            float4 t = make_float4(0.f, 0.f, 0.f, 0.f);
            if (col < HH) t = *(const float4*)(wrow + col);
            w[2 * i]     = pk2(t.x, t.y);
            w[2 * i + 1] = pk2(t.z, t.w);
        }
    }
    if (tid < 208) ((float*)sh_h)[tid] = 0.0f;

    // epilogue state (threads 0..99): cell states + gx prefetch for both rows
    float cA = 0.0f, cB = 0.0f;
    float gxA[4], gxB[4];
    size_t gxd = (size_t)dir * TT * BB * GG;
    int t0 = dir ? (TT - 1) : 0;
    if (tid < 100) {
        #pragma unroll
        for (int g = 0; g < 4; g++) {
            gxA[g] = gx[gxd + ((size_t)t0 * BB + b0r)     * GG + g * 100 + tid];
            gxB[g] = gx[gxd + ((size_t)t0 * BB + b0r + 1) * GG + g * 100 + tid];
        }
    }
    __syncthreads();

    const int base = kh * 52;
    for (int s = 0; s <= 2 * TT; s++) {
        int r = s & 1;
        // ---- GEMV: row r, time tr = s>>1 (uses h written 1 interval ago) ----
        if (s < 2 * TT) {
            const float* hrow = sh_h[r];
            unsigned long long a0 = 0, a1 = 0;
            #pragma unroll
            for (int i = 0; i < 13; i++) {
                ulonglong2 hv = *(const ulonglong2*)&hrow[base + 4 * i];
                a0 = fma2(w[2 * i],     hv.x, a0);
                a1 = fma2(w[2 * i + 1], hv.y, a1);
            }
            sg[r][kh][j] = hsum2(a0, a1);
        }
        // ---- epilogue: other row, time te = (s-1)>>1 ----
        if (s >= 1 && tid < 100) {
            int er = 1 - r;
            int te = (s - 1) >> 1;
            float g0, g1, g2, g3;
            if (er) {
                g0 = gxB[0]; g1 = gxB[1]; g2 = gxB[2]; g3 = gxB[3];
            } else {
                g0 = gxA[0]; g1 = gxA[1]; g2 = gxA[2]; g3 = gxA[3];
            }
            float gi = sg[er][0][tid]       + sg[er][1][tid]       + g0;
            float gf = sg[er][0][100 + tid] + sg[er][1][100 + tid] + g1;
            float gg = sg[er][0][200 + tid] + sg[er][1][200 + tid] + g2;
            float go = sg[er][0][300 + tid] + sg[er][1][300 + tid] + g3;
            // prefetch gx for this row's next step (in flight ~2 intervals)
            if (te + 1 < TT) {
                int tn = dir ? (TT - 2 - te) : (te + 1);
                const float* gp = gx + gxd + ((size_t)tn * BB + b0r + er) * GG + tid;
                if (er) {
                    gxB[0] = gp[0]; gxB[1] = gp[100]; gxB[2] = gp[200]; gxB[3] = gp[300];
                } else {
                    gxA[0] = gp[0]; gxA[1] = gp[100]; gxA[2] = gp[200]; gxA[3] = gp[300];
                }
            }
            float iv = fsig(gi), fv = fsig(gf), gv = ftanh(gg), ov = fsig(go);
            float c = er ? cB : cA;
            c = fv * c + iv * gv;
            if (er) cB = c; else cA = c;
            float h = ov * ftanh(c);
            sh_h[er][tid] = h;
            int tphys = dir ? (TT - 1 - te) : te;
            out[((size_t)tphys * BB + b0r + er) * outStride + dir * HH + tid] = h;
        }
        __syncthreads();
    }
}

// ---------------- launch ----------------
extern "C" void kernel_launch(void* const* d_in, const int* in_sizes, int n_in,
                              void* d_out, int out_size) {
    const float* x     = (const float*)d_in[0];
    const float* w_ih0 = (const float*)d_in[1];
    const float* w_hh0 = (const float*)d_in[2];
    const float* b0    = (const float*)d_in[3];
    const float* w_ih1 = (const float*)d_in[4];
    const float* w_hh1 = (const float*)d_in[5];
    const float* b1    = (const float*)d_in[6];
    float* out = (float*)d_out;

    float *pxT, *pgx, *pmid;
    cudaGetSymbolAddress((void**)&pxT,  g_xT);
    cudaGetSymbolAddress((void**)&pgx,  g_gx);
    cudaGetSymbolAddress((void**)&pmid, g_mid);

    // x -> xT (T,B,IN)
    transpose_x<<<dim3(TT / 32, 4, BB), dim3(32, 8)>>>(x, pxT);

    // layer 0: gx = xT @ w_ih0^T + b0 ; scan -> g_mid (stride 2H)
    gate_gemm2<100><<<148, 800>>>(pxT, IN_, w_ih0, IN_, b0, pgx);
    lstm_scan3<<<128, 800>>>(pgx, w_hh0, pmid, 2 * HH);

    // layer 1: gx = mid @ w_ih1^T + b1 (single K=200 pass) ; scan -> out
    gate_gemm2<200><<<148, 800>>>(pmid, 2 * HH, w_ih1, 2 * HH, b1, pgx);
    lstm_scan3<<<128, 800>>>(pgx, w_hh1, out, 2 * HH);
}

// round 8
// speedup vs baseline: 1.7254x; 1.7254x over previous
#include <cuda_runtime.h>
#include <cuda_bf16.h>
#include <cstdint>

// Problem constants
#define TT 1024
#define BB 128
#define HH 100
#define IN_ 100
#define GG 400   // 4*H
#define KC 100   // K-chunk for register-stationary GEMM

// ---------------- scratch (device globals: no allocs allowed) ----------------
__device__ float g_xT[(size_t)TT * BB * IN_];          // (T,B,IN)      52.4 MB
__device__ float g_gx[(size_t)2 * TT * BB * GG];       // (dir,T,B,4H) 419.4 MB
__device__ float g_mid[(size_t)TT * BB * 2 * HH];      // (T,B,2H)     104.9 MB

// ---------------- f32x2 helpers ----------------
__device__ __forceinline__ unsigned long long pk2(float a, float b) {
    unsigned long long r;
    asm("mov.b64 %0, {%1,%2};" : "=l"(r) : "f"(a), "f"(b));
    return r;
}
__device__ __forceinline__ unsigned long long fma2(unsigned long long a,
                                                   unsigned long long b,
                                                   unsigned long long c) {
    unsigned long long d;
    asm("fma.rn.f32x2 %0, %1, %2, %3;" : "=l"(d) : "l"(a), "l"(b), "l"(c));
    return d;
}
__device__ __forceinline__ float hsum2(unsigned long long a, unsigned long long b) {
    unsigned long long s;
    asm("add.rn.f32x2 %0, %1, %2;" : "=l"(s) : "l"(a), "l"(b));
    float lo, hi;
    asm("mov.b64 {%0,%1}, %2;" : "=f"(lo), "=f"(hi) : "l"(s));
    return lo + hi;
}

// ---------------- fast activations (MUFU-based, rel err ~1e-6) ----------------
__device__ __forceinline__ float fexp2(float x) {
    float r; asm("ex2.approx.f32 %0, %1;" : "=f"(r) : "f"(x)); return r;
}
__device__ __forceinline__ float frcpa(float x) {
    float r; asm("rcp.approx.f32 %0, %1;" : "=f"(r) : "f"(x)); return r;
}
__device__ __forceinline__ float fsig(float x) {
    return frcpa(1.0f + fexp2(-1.4426950408889634f * x));
}
__device__ __forceinline__ float ftanh(float x) {
    return fmaf(2.0f, frcpa(1.0f + fexp2(-2.8853900817779268f * x)), -1.0f);
}

// ---------------- kernel 1: transpose x (B,IN,T) -> xT (T,B,IN) ----------------
__global__ void transpose_x(const float* __restrict__ x, float* __restrict__ xT) {
    __shared__ float tile[32][33];
    int b  = blockIdx.z;
    int k0 = blockIdx.y * 32;
    int t0 = blockIdx.x * 32;
    int tx = threadIdx.x, ty = threadIdx.y;   // 32 x 8
    #pragma unroll
    for (int i = ty; i < 32; i += 8) {
        int k = k0 + i;
        tile[i][tx] = (k < IN_) ? x[((size_t)b * IN_ + k) * TT + (t0 + tx)] : 0.0f;
    }
    __syncthreads();
    #pragma unroll
    for (int i = ty; i < 32; i += 8) {
        int t = t0 + i, k = k0 + tx;
        if (k < IN_)
            xT[((size_t)t * BB + b) * IN_ + k] = tile[tx][i];
    }
}

// ---- secondary-gate weight loader: lane tid<128 owns gate 384+(tid>>3),
//      sixteenth e=tid&7 (cols 16e..16e+15), guarded at col<100 -------------
__device__ __forceinline__ void load_w2(unsigned long long* w2, const float* wrow,
                                        int e) {
    #pragma unroll
    for (int i = 0; i < 4; i++) {
        int col = e * 16 + 4 * i;
        float4 t = make_float4(0.f, 0.f, 0.f, 0.f);
        if (col <= 96) t = *(const float4*)(wrow + col);
        w2[2 * i]     = pk2(t.x, t.y);
        w2[2 * i + 1] = pk2(t.z, t.w);
    }
}

// ---------------- kernel 2: gx (+)= src(rows x K=100) @ W^T (+bias) ------------
// 384 threads / 12 warps -> per-SMSP 3 warps, allows 160 regs/thread.
// Thread tid owns gate tid (full K, 50 f32x2 regs). Warps 0-3 additionally cover
// gates 384..399 (one sixteenth of K per lane, shfl-combined).
__global__ __maxnreg__(160) void gate_gemm(
    const float* __restrict__ src, int srcStride,
    const float* __restrict__ Wih, int wStride, int kOff,
    const float* __restrict__ bias,
    float* __restrict__ out, int accFlag)
{
    const int M = TT * BB;               // 131072 rows per direction
    const int CPD = 74;
    const int RPC = 1776;                // rows per CTA (multiple of 16)
    int dir   = blockIdx.x / CPD;
    int chunk = blockIdx.x % CPD;
    int row0  = chunk * RPC;
    int rowHi = min(row0 + RPC, M);
    int tid = threadIdx.x;

    __shared__ __align__(16) float stage[16][128];   // cols 100..127 = 0

    // primary stationary weights + bias (gate = tid)
    unsigned long long w[KC / 2];
    {
        const float* wp = Wih + ((size_t)(dir * GG + tid)) * wStride + kOff;
        #pragma unroll
        for (int q = 0; q < KC / 2; q++) {
            float2 tv = *(const float2*)(wp + 2 * q);
            w[q] = pk2(tv.x, tv.y);
        }
    }
    float bj = bias[dir * GG + tid];

    // secondary weights (warps 0-3): gate 384+(tid>>3), sixteenth tid&7
    unsigned long long w2[8];
    float bj2 = 0.0f;
    int sgate = 384 + (tid >> 3);
    int e16 = (tid & 7) * 16;
    if (tid < 128) {
        load_w2(w2, Wih + (size_t)(dir * GG + sgate) * wStride + kOff, tid & 7);
        bj2 = bias[dir * GG + sgate];
    }

    // zero pad columns 100..127 once
    for (int i = tid; i < 16 * 28; i += 384)
        stage[i / 28][100 + i % 28] = 0.0f;

    // staging map: 400 float4 units over 384 threads (tid<16 take a 2nd unit)
    int r_ld = tid / 25,       c_ld = (tid % 25) * 4;
    int r_l2 = (384 + tid) / 25, c_l2 = ((384 + tid) % 25) * 4;
    float4 v  = make_float4(0.f, 0.f, 0.f, 0.f);
    float4 v2 = v;
    {
        int rr = min(row0 + r_ld, M - 1);
        v = *(const float4*)(src + (size_t)rr * srcStride + c_ld);
        if (tid < 16) {
            int r2 = min(row0 + r_l2, M - 1);
            v2 = *(const float4*)(src + (size_t)r2 * srcStride + c_l2);
        }
    }

    int ntiles = (rowHi - row0 + 15) / 16;
    for (int tI = 0; tI < ntiles; tI++) {
        __syncthreads();
        *(float4*)&stage[r_ld][c_ld] = v;
        if (tid < 16) *(float4*)&stage[r_l2][c_l2] = v2;
        __syncthreads();
        if (tI + 1 < ntiles) {
            int rr = min(row0 + (tI + 1) * 16 + r_ld, M - 1);
            v = *(const float4*)(src + (size_t)rr * srcStride + c_ld);
            if (tid < 16) {
                int r2 = min(row0 + (tI + 1) * 16 + r_l2, M - 1);
                v2 = *(const float4*)(src + (size_t)r2 * srcStride + c_l2);
            }
        }
        int rlim = min(16, rowHi - row0 - tI * 16);
        for (int r = 0; r < rlim; r++) {
            // primary: gate tid
            unsigned long long a0 = 0, a1 = 0;
            #pragma unroll
            for (int q = 0; q < 25; q++) {
                ulonglong2 hv = *(const ulonglong2*)&stage[r][4 * q];
                a0 = fma2(w[2 * q],     hv.x, a0);
                a1 = fma2(w[2 * q + 1], hv.y, a1);
            }
            float g = hsum2(a0, a1);
            size_t orow = (size_t)(row0 + tI * 16 + r);
            size_t oidx = ((size_t)dir * M + orow) * GG + tid;
            out[oidx] = accFlag ? (out[oidx] + g) : (g + bj);
            // secondary: warps 0-3, gates 384..399
            if (tid < 128) {
                unsigned long long s0 = 0, s1 = 0;
                ulonglong2 h0 = *(const ulonglong2*)&stage[r][e16];
                ulonglong2 h1 = *(const ulonglong2*)&stage[r][e16 + 4];
                ulonglong2 h2 = *(const ulonglong2*)&stage[r][e16 + 8];
                ulonglong2 h3 = *(const ulonglong2*)&stage[r][e16 + 12];
                s0 = fma2(w2[0], h0.x, s0); s0 = fma2(w2[1], h0.y, s0);
                s0 = fma2(w2[2], h1.x, s0); s0 = fma2(w2[3], h1.y, s0);
                s1 = fma2(w2[4], h2.x, s1); s1 = fma2(w2[5], h2.y, s1);
                s1 = fma2(w2[6], h3.x, s1); s1 = fma2(w2[7], h3.y, s1);
                float gs = hsum2(s0, s1);
                gs += __shfl_xor_sync(0xffffffffu, gs, 1);
                gs += __shfl_xor_sync(0xffffffffu, gs, 2);
                gs += __shfl_xor_sync(0xffffffffu, gs, 4);
                if ((tid & 7) == 0) {
                    size_t o2 = ((size_t)dir * M + orow) * GG + sgate;
                    out[o2] = accFlag ? (out[o2] + gs) : (gs + bj2);
                }
            }
        }
    }
}

// ---------------- kernel 3: the recurrence scan (one layer, both directions) ----
// 128 CTAs: dir = blk>>6, pair = blk&63 (2 batch rows per CTA). 384 threads.
// Thread tid owns gate tid; warps 0-3 cover gates 384..399 (sixteenth-K + shfl).
// Epilogue on tids 128..327.
__global__ __maxnreg__(160) void lstm_scan(
    const float* __restrict__ gx,     // (2,T,B,4H)
    const float* __restrict__ Whh,    // (2,4H,H)
    float* __restrict__ out)          // (T,B,2H)
{
    int dir  = blockIdx.x >> 6;
    int pair = blockIdx.x & 63;
    int b0r = pair * 2, b1r = b0r + 1;
    int tid = threadIdx.x;

    __shared__ __align__(16) float sh_h[2][128];   // cols 100..127 = 0
    __shared__ float sg[2][400];

    // primary weights (gate = tid)
    unsigned long long w[50];
    {
        const float* wp = Whh + (size_t)(dir * GG + tid) * HH;
        #pragma unroll
        for (int q = 0; q < 50; q++) {
            float2 tv = *(const float2*)(wp + 2 * q);
            w[q] = pk2(tv.x, tv.y);
        }
    }
    // secondary weights (warps 0-3)
    unsigned long long w2[8];
    int sgate = 384 + (tid >> 3);
    int e16 = (tid & 7) * 16;
    if (tid < 128)
        load_w2(w2, Whh + (size_t)(dir * GG + sgate) * HH, tid & 7);

    if (tid < 256) ((float*)sh_h)[tid] = 0.0f;

    // epilogue mapping: tids 128..327 -> (bb, uu)
    int et = tid - 128;
    int bb = et / 100, uu = et - bb * 100;     // valid for 0 <= et < 200

    float cst = 0.0f;
    int t = dir ? (TT - 1) : 0;
    size_t gxd = (size_t)dir * TT * BB * GG;

    float gA, gB;            // primary gx prefetch (gate tid)
    float gsA = 0.f, gsB = 0.f;   // secondary gx prefetch (gate sgate, lanes tid%8==0)
    gA = gx[gxd + ((size_t)t * BB + b0r) * GG + tid];
    gB = gx[gxd + ((size_t)t * BB + b1r) * GG + tid];
    if (tid < 128 && (tid & 7) == 0) {
        gsA = gx[gxd + ((size_t)t * BB + b0r) * GG + sgate];
        gsB = gx[gxd + ((size_t)t * BB + b1r) * GG + sgate];
    }
    __syncthreads();

    for (int it = 0; it < TT; it++) {
        // primary GEMV, both rows
        {
            unsigned long long a0 = 0, a1 = 0, a2 = 0, a3 = 0;
            #pragma unroll
            for (int q = 0; q < 25; q++) {
                ulonglong2 h0 = *(const ulonglong2*)&sh_h[0][4 * q];
                ulonglong2 h1 = *(const ulonglong2*)&sh_h[1][4 * q];
                a0 = fma2(w[2 * q],     h0.x, a0);
                a1 = fma2(w[2 * q + 1], h0.y, a1);
                a2 = fma2(w[2 * q],     h1.x, a2);
                a3 = fma2(w[2 * q + 1], h1.y, a3);
            }
            sg[0][tid] = gA + hsum2(a0, a1);
            sg[1][tid] = gB + hsum2(a2, a3);
        }
        // secondary GEMV (warps 0-3), both rows
        if (tid < 128) {
            ulonglong2 h00 = *(const ulonglong2*)&sh_h[0][e16];
            ulonglong2 h01 = *(const ulonglong2*)&sh_h[0][e16 + 4];
            ulonglong2 h02 = *(const ulonglong2*)&sh_h[0][e16 + 8];
            ulonglong2 h03 = *(const ulonglong2*)&sh_h[0][e16 + 12];
            ulonglong2 h10 = *(const ulonglong2*)&sh_h[1][e16];
            ulonglong2 h11 = *(const ulonglong2*)&sh_h[1][e16 + 4];
            ulonglong2 h12 = *(const ulonglong2*)&sh_h[1][e16 + 8];
            ulonglong2 h13 = *(const ulonglong2*)&sh_h[1][e16 + 12];
            unsigned long long s0 = 0, s1 = 0, s2 = 0, s3 = 0;
            s0 = fma2(w2[0], h00.x, s0); s0 = fma2(w2[1], h00.y, s0);
            s0 = fma2(w2[2], h01.x, s0); s0 = fma2(w2[3], h01.y, s0);
            s1 = fma2(w2[4], h02.x, s1); s1 = fma2(w2[5], h02.y, s1);
            s1 = fma2(w2[6], h03.x, s1); s1 = fma2(w2[7], h03.y, s1);
            s2 = fma2(w2[0], h10.x, s2); s2 = fma2(w2[1], h10.y, s2);
            s2 = fma2(w2[2], h11.x, s2); s2 = fma2(w2[3], h11.y, s2);
            s3 = fma2(w2[4], h12.x, s3); s3 = fma2(w2[5], h12.y, s3);
            s3 = fma2(w2[6], h13.x, s3); s3 = fma2(w2[7], h13.y, s3);
            float g0 = hsum2(s0, s1);
            float g1 = hsum2(s2, s3);
            g0 += __shfl_xor_sync(0xffffffffu, g0, 1);
            g0 += __shfl_xor_sync(0xffffffffu, g0, 2);
            g0 += __shfl_xor_sync(0xffffffffu, g0, 4);
            g1 += __shfl_xor_sync(0xffffffffu, g1, 1);
            g1 += __shfl_xor_sync(0xffffffffu, g1, 2);
            g1 += __shfl_xor_sync(0xffffffffu, g1, 4);
            if ((tid & 7) == 0) {
                sg[0][sgate] = gsA + g0;
                sg[1][sgate] = gsB + g1;
            }
        }
        // prefetch next step's gx
        if (it + 1 < TT) {
            int tn = dir ? (t - 1) : (t + 1);
            gA = gx[gxd + ((size_t)tn * BB + b0r) * GG + tid];
            gB = gx[gxd + ((size_t)tn * BB + b1r) * GG + tid];
            if (tid < 128 && (tid & 7) == 0) {
                gsA = gx[gxd + ((size_t)tn * BB + b0r) * GG + sgate];
                gsB = gx[gxd + ((size_t)tn * BB + b1r) * GG + sgate];
            }
        }
        __syncthreads();
        // epilogue: tids 128..327
        if (et >= 0 && et < 200) {
            float gi = sg[bb][uu];
            float gf = sg[bb][100 + uu];
            float gg = sg[bb][200 + uu];
            float go = sg[bb][300 + uu];
            float iv = fsig(gi), fv = fsig(gf), gv = ftanh(gg), ov = fsig(go);
            cst = fv * cst + iv * gv;
            float h = ov * ftanh(cst);
            sh_h[bb][uu] = h;
            int brow = bb ? b1r : b0r;
            out[((size_t)t * BB + brow) * (2 * HH) + dir * HH + uu] = h;
        }
        __syncthreads();
        t = dir ? (t - 1) : (t + 1);
    }
}

// ---------------- launch ----------------
extern "C" void kernel_launch(void* const* d_in, const int* in_sizes, int n_in,
                              void* d_out, int out_size) {
    const float* x     = (const float*)d_in[0];
    const float* w_ih0 = (const float*)d_in[1];
    const float* w_hh0 = (const float*)d_in[2];
    const float* b0    = (const float*)d_in[3];
    const float* w_ih1 = (const float*)d_in[4];
    const float* w_hh1 = (const float*)d_in[5];
    const float* b1    = (const float*)d_in[6];
    float* out = (float*)d_out;

    float *pxT, *pgx, *pmid;
    cudaGetSymbolAddress((void**)&pxT,  g_xT);
    cudaGetSymbolAddress((void**)&pgx,  g_gx);
    cudaGetSymbolAddress((void**)&pmid, g_mid);

    // x -> xT (T,B,IN)
    transpose_x<<<dim3(TT / 32, 4, BB), dim3(32, 8)>>>(x, pxT);

    // layer 0: gx = xT @ w_ih0^T + b0 ; scan -> g_mid
    gate_gemm<<<148, 384>>>(pxT, IN_, w_ih0, IN_, 0, b0, pgx, 0);
    lstm_scan<<<128, 384>>>(pgx, w_hh0, pmid);

    // layer 1: gx = mid[:, :100] @ w_ih1^T + b1, then += mid[:,100:] @ w_ih1[:,:,100:]^T
    gate_gemm<<<148, 384>>>(pmid,       2 * HH, w_ih1, 2 * HH, 0,  b1, pgx, 0);
    gate_gemm<<<148, 384>>>(pmid + HH,  2 * HH, w_ih1, 2 * HH, HH, b1, pgx, 1);
    lstm_scan<<<128, 384>>>(pgx, w_hh1, out);
}

// round 11
// speedup vs baseline: 1.9491x; 1.1296x over previous
#include <cuda_runtime.h>
#include <cuda_bf16.h>
#include <cstdint>

// Problem constants
#define TT 1024
#define BB 128
#define HH 100
#define IN_ 100
#define GG 400   // 4*H
#define KC 100   // K-chunk for register-stationary GEMM

// ---------------- scratch (device globals: no allocs allowed) ----------------
__device__ float g_xT[(size_t)TT * BB * IN_];          // (T,B,IN)      52.4 MB
__device__ float g_gx[(size_t)2 * TT * BB * GG];       // (dir,T,B,4H) 419.4 MB
__device__ float g_mid[(size_t)TT * BB * 2 * HH];      // (T,B,2H)     104.9 MB

// ---------------- f32x2 helpers ----------------
__device__ __forceinline__ unsigned long long pk2(float a, float b) {
    unsigned long long r;
    asm("mov.b64 %0, {%1,%2};" : "=l"(r) : "f"(a), "f"(b));
    return r;
}
__device__ __forceinline__ unsigned long long fma2(unsigned long long a,
                                                   unsigned long long b,
                                                   unsigned long long c) {
    unsigned long long d;
    asm("fma.rn.f32x2 %0, %1, %2, %3;" : "=l"(d) : "l"(a), "l"(b), "l"(c));
    return d;
}
__device__ __forceinline__ float hsum2(unsigned long long a, unsigned long long b) {
    unsigned long long s;
    asm("add.rn.f32x2 %0, %1, %2;" : "=l"(s) : "l"(a), "l"(b));
    float lo, hi;
    asm("mov.b64 {%0,%1}, %2;" : "=f"(lo), "=f"(hi) : "l"(s));
    return lo + hi;
}

// ---------------- fast activations (MUFU-based, rel err ~1e-6) ----------------
__device__ __forceinline__ float fexp2(float x) {
    float r; asm("ex2.approx.f32 %0, %1;" : "=f"(r) : "f"(x)); return r;
}
__device__ __forceinline__ float frcpa(float x) {
    float r; asm("rcp.approx.f32 %0, %1;" : "=f"(r) : "f"(x)); return r;
}
__device__ __forceinline__ float fsig(float x) {
    return frcpa(1.0f + fexp2(-1.4426950408889634f * x));
}
__device__ __forceinline__ float ftanh(float x) {
    return fmaf(2.0f, frcpa(1.0f + fexp2(-2.8853900817779268f * x)), -1.0f);
}

// ---------------- kernel 1: transpose x (B,IN,T) -> xT (T,B,IN) ----------------
__global__ void transpose_x(const float* __restrict__ x, float* __restrict__ xT) {
    __shared__ float tile[32][33];
    int b  = blockIdx.z;          // 0..127
    int k0 = blockIdx.y * 32;     // 0,32,64,96
    int t0 = blockIdx.x * 32;     // 0..992
    int tx = threadIdx.x, ty = threadIdx.y;   // 32 x 8
    #pragma unroll
    for (int i = ty; i < 32; i += 8) {
        int k = k0 + i;
        tile[i][tx] = (k < IN_) ? x[((size_t)b * IN_ + k) * TT + (t0 + tx)] : 0.0f;
    }
    __syncthreads();
    #pragma unroll
    for (int i = ty; i < 32; i += 8) {
        int t = t0 + i, k = k0 + tx;
        if (k < IN_)
            xT[((size_t)t * BB + b) * IN_ + k] = tile[tx][i];
    }
}

// ---------------- kernel 2: gx (+)= src(rows x K=100) @ W^T (+bias) ----------------
// R1 verbatim. Register-stationary W: thread j owns W[dir][j][kOff..kOff+99] as
// 50 f32x2 regs. Streams 16-row tiles of src through smem; broadcast reads.
__global__ __launch_bounds__(416, 1) void gate_gemm(
    const float* __restrict__ src, int srcStride,     // row stride in floats
    const float* __restrict__ Wih, int wStride, int kOff,
    const float* __restrict__ bias,
    float* __restrict__ out, int accFlag)
{
    const int M = TT * BB;               // 131072 rows per direction
    const int CPD = 74;                  // CTAs per direction (grid = 148)
    const int RPC = 1776;                // rows per CTA (multiple of 16; 74*1776 >= M)
    int dir   = blockIdx.x / CPD;
    int chunk = blockIdx.x % CPD;
    int row0  = chunk * RPC;
    int rowHi = min(row0 + RPC, M);
    int j = threadIdx.x;

    __shared__ float stage[16][100];     // 6.4 KB row tile

    // load stationary weights + bias
    unsigned long long w[KC / 2];
    float bj = 0.0f;
    if (j < GG) {
        const float* wp = Wih + ((size_t)(dir * GG + j)) * wStride + kOff;
        #pragma unroll
        for (int q = 0; q < KC / 2; q++) {
            float2 tv = *(const float2*)(wp + 2 * q);
            w[q] = pk2(tv.x, tv.y);
        }
        bj = bias[dir * GG + j];
    }

    // tile prefetch mapping: thread j<400 -> (row r_ld, float4 q_ld)
    int r_ld = j / 25;
    int q_ld = (j % 25) * 4;
    float4 v = make_float4(0.f, 0.f, 0.f, 0.f);
    if (j < 400) {
        int rr = min(row0 + r_ld, M - 1);
        v = *(const float4*)(src + (size_t)rr * srcStride + q_ld);
    }

    int ntiles = (rowHi - row0 + 15) / 16;
    for (int tI = 0; tI < ntiles; tI++) {
        __syncthreads();                      // prior tile's readers done
        if (j < 400) *(float4*)&stage[r_ld][q_ld] = v;
        __syncthreads();                      // stage ready
        if (j < 400 && tI + 1 < ntiles) {     // prefetch next tile (overlaps compute)
            int rr = min(row0 + (tI + 1) * 16 + r_ld, M - 1);
            v = *(const float4*)(src + (size_t)rr * srcStride + q_ld);
        }
        if (j < GG) {
            int rlim = min(16, rowHi - row0 - tI * 16);
            for (int r = 0; r < rlim; r++) {
                unsigned long long a0 = 0, a1 = 0;
                #pragma unroll
                for (int q = 0; q < 25; q++) {
                    ulonglong2 hv = *(const ulonglong2*)&stage[r][4 * q];
                    a0 = fma2(w[2 * q],     hv.x, a0);
                    a1 = fma2(w[2 * q + 1], hv.y, a1);
                }
                float g = hsum2(a0, a1);
                size_t orow = (size_t)(row0 + tI * 16 + r);
                size_t oidx = ((size_t)dir * M + orow) * GG + j;
                out[oidx] = accFlag ? (out[oidx] + g) : (g + bj);
            }
        }
    }
}

// ---------------- kernel 3: the recurrence scan (one layer, both directions) ----
// R1 structure, ONE change: gate activations (sigmoid/tanh) are applied by the
// GEMV threads BEFORE barrier 1 (spread over all 13 warps, overlapping FFMA/LDS),
// instead of inside the 200-thread epilogue critical section. The epilogue keeps
// only c = f*c + i*g and h = o*tanh(c) (one MUFU chain instead of four).
__global__ __launch_bounds__(416, 1) void lstm_scan(
    const float* __restrict__ gx,     // (2,T,B,4H)
    const float* __restrict__ Whh,    // (2,4H,H)
    float* __restrict__ out)          // (T,B,2H)
{
    int dir  = blockIdx.x >> 6;
    int pair = blockIdx.x & 63;
    int b0r = pair * 2, b1r = b0r + 1;
    int j = threadIdx.x;

    __shared__ float sh_h[2][100];    // current h for both rows
    __shared__ float sg[2][400];      // ACTIVATED gate exchange

    unsigned long long w[50];
    if (j < 400) {
        const float* wp = Whh + (size_t)(dir * GG + j) * HH;
        #pragma unroll
        for (int q = 0; q < 50; q++) {
            float2 tv = *(const float2*)(wp + 2 * q);
            w[q] = pk2(tv.x, tv.y);
        }
    }
    if (j < 100) { sh_h[0][j] = 0.0f; sh_h[1][j] = 0.0f; }

    // is this thread's gate the "g" gate (tanh) or i/f/o (sigmoid)?
    bool isTanh = (j >= 200 && j < 300);

    float cst = 0.0f;                 // cell state (epilogue threads only)
    int bb = j / 100;                 // 0 or 1 for j<200
    int uu = j - bb * 100;

    int t = dir ? (TT - 1) : 0;
    size_t gxd = (size_t)dir * TT * BB * GG;
    float gA = 0.0f, gB = 0.0f;
    if (j < 400) {                    // prefetch first step's gx
        gA = gx[gxd + ((size_t)t * BB + b0r) * GG + j];
        gB = gx[gxd + ((size_t)t * BB + b1r) * GG + j];
    }
    __syncthreads();

    for (int it = 0; it < TT; it++) {
        if (j < 400) {
            unsigned long long a0 = 0, a1 = 0, a2 = 0, a3 = 0;
            #pragma unroll
            for (int q = 0; q < 25; q++) {
                ulonglong2 h0 = *(const ulonglong2*)&sh_h[0][4 * q];
                ulonglong2 h1 = *(const ulonglong2*)&sh_h[1][4 * q];
                a0 = fma2(w[2 * q],     h0.x, a0);
                a1 = fma2(w[2 * q + 1], h0.y, a1);
                a2 = fma2(w[2 * q],     h1.x, a2);
                a3 = fma2(w[2 * q + 1], h1.y, a3);
            }
            float g0 = gA + hsum2(a0, a1);
            float g1 = gB + hsum2(a2, a3);
            // activation hoisted into the GEMV phase (all warps, overlapped)
            sg[0][j] = isTanh ? ftanh(g0) : fsig(g0);
            sg[1][j] = isTanh ? ftanh(g1) : fsig(g1);
            if (it + 1 < TT) {        // prefetch next step's gx
                int tn = dir ? (t - 1) : (t + 1);
                gA = gx[gxd + ((size_t)tn * BB + b0r) * GG + j];
                gB = gx[gxd + ((size_t)tn * BB + b1r) * GG + j];
            }
        }
        __syncthreads();
        if (j < 200) {
            float iv = sg[bb][uu];            // already sigmoid'd
            float fv = sg[bb][100 + uu];      // already sigmoid'd
            float gv = sg[bb][200 + uu];      // already tanh'd
            float ov = sg[bb][300 + uu];      // already sigmoid'd
            cst = fv * cst + iv * gv;
            float h = ov * ftanh(cst);
            sh_h[bb][uu] = h;
            int brow = bb ? b1r : b0r;
            out[((size_t)t * BB + brow) * (2 * HH) + dir * HH + uu] = h;
        }
        __syncthreads();
        t = dir ? (t - 1) : (t + 1);
    }
}

// ---------------- launch ----------------
extern "C" void kernel_launch(void* const* d_in, const int* in_sizes, int n_in,
                              void* d_out, int out_size) {
    const float* x     = (const float*)d_in[0];
    const float* w_ih0 = (const float*)d_in[1];
    const float* w_hh0 = (const float*)d_in[2];
    const float* b0    = (const float*)d_in[3];
    const float* w_ih1 = (const float*)d_in[4];
    const float* w_hh1 = (const float*)d_in[5];
    const float* b1    = (const float*)d_in[6];
    float* out = (float*)d_out;

    float *pxT, *pgx, *pmid;
    cudaGetSymbolAddress((void**)&pxT,  g_xT);
    cudaGetSymbolAddress((void**)&pgx,  g_gx);
    cudaGetSymbolAddress((void**)&pmid, g_mid);

    // x -> xT (T,B,IN)
    transpose_x<<<dim3(TT / 32, 4, BB), dim3(32, 8)>>>(x, pxT);

    // layer 0: gx = xT @ w_ih0^T + b0 ; scan -> g_mid
    gate_gemm<<<148, 416>>>(pxT, IN_, w_ih0, IN_, 0, b0, pgx, 0);
    lstm_scan<<<128, 416>>>(pgx, w_hh0, pmid);

    // layer 1: gx = mid[:, :100] @ w_ih1[:, :, :100]^T + b1, then += mid[:,100:] @ w_ih1[:,:,100:]^T
    gate_gemm<<<148, 416>>>(pmid,       2 * HH, w_ih1, 2 * HH, 0,  b1, pgx, 0);
    gate_gemm<<<148, 416>>>(pmid + HH,  2 * HH, w_ih1, 2 * HH, HH, b1, pgx, 1);
    lstm_scan<<<128, 416>>>(pgx, w_hh1, out);
}

// round 12
// speedup vs baseline: 2.0501x; 1.0518x over previous
#include <cuda_runtime.h>
#include <cuda_bf16.h>
#include <cstdint>

// Problem constants
#define TT 1024
#define BB 128
#define HH 100
#define IN_ 100
#define GG 400   // 4*H

// ---------------- scratch (device globals: no allocs allowed) ----------------
__device__ float g_xT[(size_t)TT * BB * IN_];          // (T,B,IN)      52.4 MB
__device__ float g_gx[(size_t)2 * TT * BB * GG];       // (dir,T,B,4H) 419.4 MB
__device__ float g_mid[(size_t)TT * BB * 2 * HH];      // (T,B,2H)     104.9 MB

// ---------------- f32x2 helpers ----------------
__device__ __forceinline__ unsigned long long pk2(float a, float b) {
    unsigned long long r;
    asm("mov.b64 %0, {%1,%2};" : "=l"(r) : "f"(a), "f"(b));
    return r;
}
__device__ __forceinline__ unsigned long long fma2(unsigned long long a,
                                                   unsigned long long b,
                                                   unsigned long long c) {
    unsigned long long d;
    asm("fma.rn.f32x2 %0, %1, %2, %3;" : "=l"(d) : "l"(a), "l"(b), "l"(c));
    return d;
}
__device__ __forceinline__ float hsum2(unsigned long long a, unsigned long long b) {
    unsigned long long s;
    asm("add.rn.f32x2 %0, %1, %2;" : "=l"(s) : "l"(a), "l"(b));
    float lo, hi;
    asm("mov.b64 {%0,%1}, %2;" : "=f"(lo), "=f"(hi) : "l"(s));
    return lo + hi;
}
__device__ __forceinline__ void unpk2(float& lo, float& hi, unsigned long long v) {
    asm("mov.b64 {%0,%1}, %2;" : "=f"(lo), "=f"(hi) : "l"(v));
}

// ---------------- fast activations (MUFU-based, rel err ~1e-6) ----------------
__device__ __forceinline__ float fexp2(float x) {
    float r; asm("ex2.approx.f32 %0, %1;" : "=f"(r) : "f"(x)); return r;
}
__device__ __forceinline__ float frcpa(float x) {
    float r; asm("rcp.approx.f32 %0, %1;" : "=f"(r) : "f"(x)); return r;
}
__device__ __forceinline__ float fsig(float x) {
    return frcpa(1.0f + fexp2(-1.4426950408889634f * x));
}
__device__ __forceinline__ float ftanh(float x) {
    return fmaf(2.0f, frcpa(1.0f + fexp2(-2.8853900817779268f * x)), -1.0f);
}

// ---------------- kernel 1: transpose x (B,IN,T) -> xT (T,B,IN) ----------------
__global__ void transpose_x(const float* __restrict__ x, float* __restrict__ xT) {
    __shared__ float tile[32][33];
    int b  = blockIdx.z;
    int k0 = blockIdx.y * 32;
    int t0 = blockIdx.x * 32;
    int tx = threadIdx.x, ty = threadIdx.y;   // 32 x 8
    #pragma unroll
    for (int i = ty; i < 32; i += 8) {
        int k = k0 + i;
        tile[i][tx] = (k < IN_) ? x[((size_t)b * IN_ + k) * TT + (t0 + tx)] : 0.0f;
    }
    __syncthreads();
    #pragma unroll
    for (int i = ty; i < 32; i += 8) {
        int t = t0 + i, k = k0 + tx;
        if (k < IN_)
            xT[((size_t)t * BB + b) * IN_ + k] = tile[tx][i];
    }
}

// ---------------- kernel 2: tiled gate GEMM -------------------------------------
// gx[dir][row][g] = sum_k src[row][k] * W[dir][g][k] + bias[dir][g]
// CTA tile: 64 rows x 64 gates. 256 threads, thread tile 4 rows x 4 gates held in
// 8 f32x2 accumulators (row pairs). A and B staged in smem as [k][unit] with
// stride 68 floats (bank spread + 16B alignment). ~55 regs/thread -> multiple
// CTAs co-resident per SM (the latency hiding the register-stationary design
// structurally forbids). grid = (rowTiles=2048, gateTiles=7, dir=2); gate tile 6
// covers gates 384..399 (stage zero-pads, stores guarded).
template<int K>
__global__ void gemm_tile(
    const float* __restrict__ src,    // (M, K) row-major
    const float* __restrict__ W,      // (2, 400, K) row-major
    const float* __restrict__ bias,   // (2, 400)
    float* __restrict__ gx)           // (2, M, 400)
{
    constexpr int LDT = 68;                    // smem row stride (floats)
    constexpr int Q4  = K / 4;                 // float4 units per source row
    const int M = TT * BB;

    extern __shared__ float sm[];
    float* As = sm;                            // [K][68], cols 0..63 used (rows)
    float* Bs = sm + K * LDT;                  // [K][68], cols 0..63 used (gates)

    int rt0 = blockIdx.x * 64;
    int g0  = blockIdx.y * 64;
    int dir = blockIdx.z;
    int tid = threadIdx.x;

    // ---- stage A: 64 rows x K, transposed into [k][row] ----
    for (int i = tid; i < 64 * Q4; i += 256) {
        int r = i / Q4, q = i - r * Q4;
        float4 v = *(const float4*)(src + (size_t)(rt0 + r) * K + 4 * q);
        As[(4 * q + 0) * LDT + r] = v.x;
        As[(4 * q + 1) * LDT + r] = v.y;
        As[(4 * q + 2) * LDT + r] = v.z;
        As[(4 * q + 3) * LDT + r] = v.w;
    }
    // ---- stage B: 64 gates x K, transposed into [k][gate] (zero-pad g>=400) ----
    for (int i = tid; i < 64 * Q4; i += 256) {
        int g = i / Q4, q = i - g * Q4;
        int gate = g0 + g;
        float4 v = make_float4(0.f, 0.f, 0.f, 0.f);
        if (gate < GG)
            v = *(const float4*)(W + (size_t)(dir * GG + gate) * K + 4 * q);
        Bs[(4 * q + 0) * LDT + g] = v.x;
        Bs[(4 * q + 1) * LDT + g] = v.y;
        Bs[(4 * q + 2) * LDT + g] = v.z;
        Bs[(4 * q + 3) * LDT + g] = v.w;
    }
    __syncthreads();

    int tg = (tid & 15) * 4;    // gate offset within tile (0..60)
    int tr = (tid >> 4) * 4;    // row offset within tile  (0..60)

    unsigned long long c0[4] = {0, 0, 0, 0};   // rows (tr, tr+1) x 4 gates
    unsigned long long c1[4] = {0, 0, 0, 0};   // rows (tr+2, tr+3) x 4 gates

    #pragma unroll 4
    for (int k = 0; k < K; k++) {
        ulonglong2 ap = *(const ulonglong2*)&As[k * LDT + tr];   // rows tr..tr+3
        float4 b4 = *(const float4*)&Bs[k * LDT + tg];
        unsigned long long b0 = pk2(b4.x, b4.x);
        unsigned long long b1 = pk2(b4.y, b4.y);
        unsigned long long b2 = pk2(b4.z, b4.z);
        unsigned long long b3 = pk2(b4.w, b4.w);
        c0[0] = fma2(ap.x, b0, c0[0]);  c1[0] = fma2(ap.y, b0, c1[0]);
        c0[1] = fma2(ap.x, b1, c0[1]);  c1[1] = fma2(ap.y, b1, c1[1]);
        c0[2] = fma2(ap.x, b2, c0[2]);  c1[2] = fma2(ap.y, b2, c1[2]);
        c0[3] = fma2(ap.x, b3, c0[3]);  c1[3] = fma2(ap.y, b3, c1[3]);
    }

    // ---- store: 4 rows x 4 gates (+bias), guarded on gate tail ----
    if (g0 + tg < GG) {
        float4 bi = *(const float4*)(bias + dir * GG + g0 + tg);
        float r0g[4], r1g[4], r2g[4], r3g[4];
        #pragma unroll
        for (int g = 0; g < 4; g++) {
            unpk2(r0g[g], r1g[g], c0[g]);
            unpk2(r2g[g], r3g[g], c1[g]);
        }
        size_t base = ((size_t)dir * M + rt0 + tr) * GG + g0 + tg;
        float4 o;
        o.x = r0g[0] + bi.x; o.y = r0g[1] + bi.y; o.z = r0g[2] + bi.z; o.w = r0g[3] + bi.w;
        *(float4*)(gx + base + 0 * GG) = o;
        o.x = r1g[0] + bi.x; o.y = r1g[1] + bi.y; o.z = r1g[2] + bi.z; o.w = r1g[3] + bi.w;
        *(float4*)(gx + base + 1 * GG) = o;
        o.x = r2g[0] + bi.x; o.y = r2g[1] + bi.y; o.z = r2g[2] + bi.z; o.w = r2g[3] + bi.w;
        *(float4*)(gx + base + 2 * GG) = o;
        o.x = r3g[0] + bi.x; o.y = r3g[1] + bi.y; o.z = r3g[2] + bi.z; o.w = r3g[3] + bi.w;
        *(float4*)(gx + base + 3 * GG) = o;
    }
}

// ---------------- kernel 3: the recurrence scan (R1 verbatim — best known) ------
__global__ __launch_bounds__(416, 1) void lstm_scan(
    const float* __restrict__ gx,     // (2,T,B,4H)
    const float* __restrict__ Whh,    // (2,4H,H)
    float* __restrict__ out)          // (T,B,2H)
{
    int dir  = blockIdx.x >> 6;
    int pair = blockIdx.x & 63;
    int b0r = pair * 2, b1r = b0r + 1;
    int j = threadIdx.x;

    __shared__ float sh_h[2][100];    // current h for both rows
    __shared__ float sg[2][400];      // gate exchange

    unsigned long long w[50];
    if (j < 400) {
        const float* wp = Whh + (size_t)(dir * GG + j) * HH;
        #pragma unroll
        for (int q = 0; q < 50; q++) {
            float2 tv = *(const float2*)(wp + 2 * q);
            w[q] = pk2(tv.x, tv.y);
        }
    }
    if (j < 100) { sh_h[0][j] = 0.0f; sh_h[1][j] = 0.0f; }

    float cst = 0.0f;                 // cell state (epilogue threads only)
    int bb = j / 100;                 // 0 or 1 for j<200
    int uu = j - bb * 100;

    int t = dir ? (TT - 1) : 0;
    size_t gxd = (size_t)dir * TT * BB * GG;
    float gA = 0.0f, gB = 0.0f;
    if (j < 400) {                    // prefetch first step's gx
        gA = gx[gxd + ((size_t)t * BB + b0r) * GG + j];
        gB = gx[gxd + ((size_t)t * BB + b1r) * GG + j];
    }
    __syncthreads();

    for (int it = 0; it < TT; it++) {
        if (j < 400) {
            unsigned long long a0 = 0, a1 = 0, a2 = 0, a3 = 0;
            #pragma unroll
            for (int q = 0; q < 25; q++) {
                ulonglong2 h0 = *(const ulonglong2*)&sh_h[0][4 * q];
                ulonglong2 h1 = *(const ulonglong2*)&sh_h[1][4 * q];
                a0 = fma2(w[2 * q],     h0.x, a0);
                a1 = fma2(w[2 * q + 1], h0.y, a1);
                a2 = fma2(w[2 * q],     h1.x, a2);
                a3 = fma2(w[2 * q + 1], h1.y, a3);
            }
            sg[0][j] = gA + hsum2(a0, a1);
            sg[1][j] = gB + hsum2(a2, a3);
            if (it + 1 < TT) {        // prefetch next step's gx
                int tn = dir ? (t - 1) : (t + 1);
                gA = gx[gxd + ((size_t)tn * BB + b0r) * GG + j];
                gB = gx[gxd + ((size_t)tn * BB + b1r) * GG + j];
            }
        }
        __syncthreads();
        if (j < 200) {
            float gi = sg[bb][uu];
            float gf = sg[bb][100 + uu];
            float gg = sg[bb][200 + uu];
            float go = sg[bb][300 + uu];
            float iv = fsig(gi), fv = fsig(gf), gv = ftanh(gg), ov = fsig(go);
            cst = fv * cst + iv * gv;
            float h = ov * ftanh(cst);
            sh_h[bb][uu] = h;
            int brow = bb ? b1r : b0r;
            out[((size_t)t * BB + brow) * (2 * HH) + dir * HH + uu] = h;
        }
        __syncthreads();
        t = dir ? (t - 1) : (t + 1);
    }
}

// ---------------- launch ----------------
extern "C" void kernel_launch(void* const* d_in, const int* in_sizes, int n_in,
                              void* d_out, int out_size) {
    const float* x     = (const float*)d_in[0];
    const float* w_ih0 = (const float*)d_in[1];
    const float* w_hh0 = (const float*)d_in[2];
    const float* b0    = (const float*)d_in[3];
    const float* w_ih1 = (const float*)d_in[4];
    const float* w_hh1 = (const float*)d_in[5];
    const float* b1    = (const float*)d_in[6];
    float* out = (float*)d_out;

    float *pxT, *pgx, *pmid;
    cudaGetSymbolAddress((void**)&pxT,  g_xT);
    cudaGetSymbolAddress((void**)&pgx,  g_gx);
    cudaGetSymbolAddress((void**)&pmid, g_mid);

    const int SM100 = 2 * 100 * 68 * 4;   // 54.4 KB
    const int SM200 = 2 * 200 * 68 * 4;   // 108.8 KB
    cudaFuncSetAttribute(gemm_tile<100>, cudaFuncAttributeMaxDynamicSharedMemorySize, SM100);
    cudaFuncSetAttribute(gemm_tile<200>, cudaFuncAttributeMaxDynamicSharedMemorySize, SM200);

    // x -> xT (T,B,IN)
    transpose_x<<<dim3(TT / 32, 4, BB), dim3(32, 8)>>>(x, pxT);

    // layer 0: gx = xT @ w_ih0^T + b0 (tiled GEMM) ; scan -> g_mid
    gemm_tile<100><<<dim3(TT * BB / 64, 7, 2), 256, SM100>>>(pxT, w_ih0, b0, pgx);
    lstm_scan<<<128, 416>>>(pgx, w_hh0, pmid);

    // layer 1: gx = mid @ w_ih1^T + b1 (single K=200 tiled GEMM) ; scan -> out
    gemm_tile<200><<<dim3(TT * BB / 64, 7, 2), 256, SM200>>>(pmid, w_ih1, b1, pgx);
    lstm_scan<<<128, 416>>>(pgx, w_hh1, out);
}

// round 17
// speedup vs baseline: 2.5843x; 1.2606x over previous
#include <cuda_runtime.h>
#include <cuda_bf16.h>
#include <cstdint>

// Problem constants
#define TT 1024
#define BB 128
#define HH 100
#define IN_ 100
#define GG 400   // 4*H

// ---------------- scratch (device globals: no allocs allowed) ----------------
__device__ float g_xT[(size_t)TT * BB * IN_];          // (T,B,IN)      52.4 MB
__device__ float g_gx[(size_t)2 * TT * BB * GG];       // (dir,T,B,4H) 419.4 MB
__device__ float g_mid[(size_t)TT * BB * 2 * HH];      // (T,B,2H)     104.9 MB

// ---------------- f32x2 helpers ----------------
__device__ __forceinline__ unsigned long long pk2(float a, float b) {
    unsigned long long r;
    asm("mov.b64 %0, {%1,%2};" : "=l"(r) : "f"(a), "f"(b));
    return r;
}
__device__ __forceinline__ unsigned long long fma2(unsigned long long a,
                                                   unsigned long long b,
                                                   unsigned long long c) {
    unsigned long long d;
    asm("fma.rn.f32x2 %0, %1, %2, %3;" : "=l"(d) : "l"(a), "l"(b), "l"(c));
    return d;
}
__device__ __forceinline__ float hsum2(unsigned long long a, unsigned long long b) {
    unsigned long long s;
    asm("add.rn.f32x2 %0, %1, %2;" : "=l"(s) : "l"(a), "l"(b));
    float lo, hi;
    asm("mov.b64 {%0,%1}, %2;" : "=f"(lo), "=f"(hi) : "l"(s));
    return lo + hi;
}
__device__ __forceinline__ void unpk2(float& lo, float& hi, unsigned long long v) {
    asm("mov.b64 {%0,%1}, %2;" : "=f"(lo), "=f"(hi) : "l"(v));
}

// ---------------- fast activations (MUFU-based, rel err ~1e-6) ----------------
__device__ __forceinline__ float fexp2(float x) {
    float r; asm("ex2.approx.f32 %0, %1;" : "=f"(r) : "f"(x)); return r;
}
__device__ __forceinline__ float frcpa(float x) {
    float r; asm("rcp.approx.f32 %0, %1;" : "=f"(r) : "f"(x)); return r;
}
__device__ __forceinline__ float fsig(float x) {
    return frcpa(1.0f + fexp2(-1.4426950408889634f * x));
}
__device__ __forceinline__ float ftanh(float x) {
    return fmaf(2.0f, frcpa(1.0f + fexp2(-2.8853900817779268f * x)), -1.0f);
}

// ---------------- kernel 1: transpose x (B,IN,T) -> xT (T,B,IN) ----------------
__global__ void transpose_x(const float* __restrict__ x, float* __restrict__ xT) {
    __shared__ float tile[32][33];
    int b  = blockIdx.z;
    int k0 = blockIdx.y * 32;
    int t0 = blockIdx.x * 32;
    int tx = threadIdx.x, ty = threadIdx.y;   // 32 x 8
    #pragma unroll
    for (int i = ty; i < 32; i += 8) {
        int k = k0 + i;
        tile[i][tx] = (k < IN_) ? x[((size_t)b * IN_ + k) * TT + (t0 + tx)] : 0.0f;
    }
    __syncthreads();
    #pragma unroll
    for (int i = ty; i < 32; i += 8) {
        int t = t0 + i, k = k0 + tx;
        if (k < IN_)
            xT[((size_t)t * BB + b) * IN_ + k] = tile[tx][i];
    }
}

// ---------------- kernel 2: tiled gate GEMM, 8x4 thread tile --------------------
// gx[dir][row][g] = sum_k src[row][k] * W[dir][g][k] + bias[dir][g]
// CTA tile: 128 rows x 64 gates, 256 threads; thread tile 8 rows x 4 gates in
// 16 f32x2 accumulators. K staged in chunks of 100 ([k][unit] transposed smem,
// conflict-free STS via row-major thread map). 80KB smem -> 2 CTAs/SM.
// Per k per thread: 2 LDS.128 (a, broadcast) + 1 LDS.128 (b) + 4 splats
// + 16 fma2 -> fma-pipe-bound (~128 MAC/cyc/SM floor).
template<int K>
__global__ void gemm_tile8(
    const float* __restrict__ src,    // (M, K) row-major
    const float* __restrict__ W,      // (2, 400, K) row-major
    const float* __restrict__ bias,   // (2, 400)
    float* __restrict__ gx)           // (2, M, 400)
{
    constexpr int NCH = K / 100;              // K chunks of 100
    constexpr int LDA = 132;                  // A smem stride (128 rows + pad)
    constexpr int LDB = 68;                   // B smem stride (64 gates + pad)
    const int M = TT * BB;

    extern __shared__ float sm[];
    float* As = sm;                           // [100][132]
    float* Bs = sm + 100 * LDA;               // [100][68]

    int rt0 = blockIdx.x * 128;
    int g0  = blockIdx.y * 64;
    int dir = blockIdx.z;
    int tid = threadIdx.x;

    int tg = (tid & 15) * 4;     // gate offset (0..60)
    int tr = (tid >> 4) * 8;     // row offset  (0..120)

    unsigned long long c[16];    // c[g*4 + p]: gate tg+g, rows (tr+2p, tr+2p+1)
    #pragma unroll
    for (int i = 0; i < 16; i++) c[i] = 0;

    for (int ch = 0; ch < NCH; ch++) {
        int k0 = ch * 100;
        if (ch) __syncthreads();              // protect prev chunk's readers
        // ---- stage A: 128 rows x 100 k, transposed [k][row] (conflict-free) ----
        for (int i = tid; i < 128 * 25; i += 256) {
            int r = i & 127, q = i >> 7;
            float4 v = *(const float4*)(src + (size_t)(rt0 + r) * K + k0 + 4 * q);
            As[(4 * q + 0) * LDA + r] = v.x;
            As[(4 * q + 1) * LDA + r] = v.y;
            As[(4 * q + 2) * LDA + r] = v.z;
            As[(4 * q + 3) * LDA + r] = v.w;
        }
        // ---- stage B: 64 gates x 100 k, transposed [k][gate] (zero-pad tail) ----
        for (int i = tid; i < 64 * 25; i += 256) {
            int g = i & 63, q = i >> 6;
            int gate = g0 + g;
            float4 v = make_float4(0.f, 0.f, 0.f, 0.f);
            if (gate < GG)
                v = *(const float4*)(W + (size_t)(dir * GG + gate) * K + k0 + 4 * q);
            Bs[(4 * q + 0) * LDB + g] = v.x;
            Bs[(4 * q + 1) * LDB + g] = v.y;
            Bs[(4 * q + 2) * LDB + g] = v.z;
            Bs[(4 * q + 3) * LDB + g] = v.w;
        }
        __syncthreads();

        #pragma unroll 2
        for (int k = 0; k < 100; k++) {
            ulonglong2 a01 = *(const ulonglong2*)&As[k * LDA + tr];      // rows tr..tr+3
            ulonglong2 a23 = *(const ulonglong2*)&As[k * LDA + tr + 4];  // rows tr+4..tr+7
            float4 b4 = *(const float4*)&Bs[k * LDB + tg];
            unsigned long long b0 = pk2(b4.x, b4.x);
            unsigned long long b1 = pk2(b4.y, b4.y);
            unsigned long long b2 = pk2(b4.z, b4.z);
            unsigned long long b3 = pk2(b4.w, b4.w);
            c[0]  = fma2(a01.x, b0, c[0]);   c[1]  = fma2(a01.y, b0, c[1]);
            c[2]  = fma2(a23.x, b0, c[2]);   c[3]  = fma2(a23.y, b0, c[3]);
            c[4]  = fma2(a01.x, b1, c[4]);   c[5]  = fma2(a01.y, b1, c[5]);
            c[6]  = fma2(a23.x, b1, c[6]);   c[7]  = fma2(a23.y, b1, c[7]);
            c[8]  = fma2(a01.x, b2, c[8]);   c[9]  = fma2(a01.y, b2, c[9]);
            c[10] = fma2(a23.x, b2, c[10]);  c[11] = fma2(a23.y, b2, c[11]);
            c[12] = fma2(a01.x, b3, c[12]);  c[13] = fma2(a01.y, b3, c[13]);
            c[14] = fma2(a23.x, b3, c[14]);  c[15] = fma2(a23.y, b3, c[15]);
        }
    }

    // ---- store: 8 rows x 4 gates (+bias), guarded on gate tail ----
    if (g0 + tg < GG) {
        float4 bi = *(const float4*)(bias + dir * GG + g0 + tg);
        size_t base = ((size_t)dir * M + rt0 + tr) * GG + g0 + tg;
        #pragma unroll
        for (int p = 0; p < 4; p++) {
            float lo0, hi0, lo1, hi1, lo2, hi2, lo3, hi3;
            unpk2(lo0, hi0, c[0 * 4 + p]);
            unpk2(lo1, hi1, c[1 * 4 + p]);
            unpk2(lo2, hi2, c[2 * 4 + p]);
            unpk2(lo3, hi3, c[3 * 4 + p]);
            float4 o;
            o.x = lo0 + bi.x; o.y = lo1 + bi.y; o.z = lo2 + bi.z; o.w = lo3 + bi.w;
            *(float4*)(gx + base + (size_t)(2 * p) * GG) = o;
            o.x = hi0 + bi.x; o.y = hi1 + bi.y; o.z = hi2 + bi.z; o.w = hi3 + bi.w;
            *(float4*)(gx + base + (size_t)(2 * p + 1) * GG) = o;
        }
    }
}

// ---------------- kernel 3: the recurrence scan (R1 verbatim — best known) ------
__global__ __launch_bounds__(416, 1) void lstm_scan(
    const float* __restrict__ gx,     // (2,T,B,4H)
    const float* __restrict__ Whh,    // (2,4H,H)
    float* __restrict__ out)          // (T,B,2H)
{
    int dir  = blockIdx.x >> 6;
    int pair = blockIdx.x & 63;
    int b0r = pair * 2, b1r = b0r + 1;
    int j = threadIdx.x;

    __shared__ float sh_h[2][100];    // current h for both rows
    __shared__ float sg[2][400];      // gate exchange

    unsigned long long w[50];
    if (j < 400) {
        const float* wp = Whh + (size_t)(dir * GG + j) * HH;
        #pragma unroll
        for (int q = 0; q < 50; q++) {
            float2 tv = *(const float2*)(wp + 2 * q);
            w[q] = pk2(tv.x, tv.y);
        }
    }
    if (j < 100) { sh_h[0][j] = 0.0f; sh_h[1][j] = 0.0f; }

    float cst = 0.0f;                 // cell state (epilogue threads only)
    int bb = j / 100;                 // 0 or 1 for j<200
    int uu = j - bb * 100;

    int t = dir ? (TT - 1) : 0;
    size_t gxd = (size_t)dir * TT * BB * GG;
    float gA = 0.0f, gB = 0.0f;
    if (j < 400) {                    // prefetch first step's gx
        gA = gx[gxd + ((size_t)t * BB + b0r) * GG + j];
        gB = gx[gxd + ((size_t)t * BB + b1r) * GG + j];
    }
    __syncthreads();

    for (int it = 0; it < TT; it++) {
        if (j < 400) {
            unsigned long long a0 = 0, a1 = 0, a2 = 0, a3 = 0;
            #pragma unroll
            for (int q = 0; q < 25; q++) {
                ulonglong2 h0 = *(const ulonglong2*)&sh_h[0][4 * q];
                ulonglong2 h1 = *(const ulonglong2*)&sh_h[1][4 * q];
                a0 = fma2(w[2 * q],     h0.x, a0);
                a1 = fma2(w[2 * q + 1], h0.y, a1);
                a2 = fma2(w[2 * q],     h1.x, a2);
                a3 = fma2(w[2 * q + 1], h1.y, a3);
            }
            sg[0][j] = gA + hsum2(a0, a1);
            sg[1][j] = gB + hsum2(a2, a3);
            if (it + 1 < TT) {        // prefetch next step's gx
                int tn = dir ? (t - 1) : (t + 1);
                gA = gx[gxd + ((size_t)tn * BB + b0r) * GG + j];
                gB = gx[gxd + ((size_t)tn * BB + b1r) * GG + j];
            }
        }
        __syncthreads();
        if (j < 200) {
            float gi = sg[bb][uu];
            float gf = sg[bb][100 + uu];
            float gg = sg[bb][200 + uu];
            float go = sg[bb][300 + uu];
            float iv = fsig(gi), fv = fsig(gf), gv = ftanh(gg), ov = fsig(go);
            cst = fv * cst + iv * gv;
            float h = ov * ftanh(cst);
            sh_h[bb][uu] = h;
            int brow = bb ? b1r : b0r;
            out[((size_t)t * BB + brow) * (2 * HH) + dir * HH + uu] = h;
        }
        __syncthreads();
        t = dir ? (t - 1) : (t + 1);
    }
}

// ---------------- launch ----------------
extern "C" void kernel_launch(void* const* d_in, const int* in_sizes, int n_in,
                              void* d_out, int out_size) {
    const float* x     = (const float*)d_in[0];
    const float* w_ih0 = (const float*)d_in[1];
    const float* w_hh0 = (const float*)d_in[2];
    const float* b0    = (const float*)d_in[3];
    const float* w_ih1 = (const float*)d_in[4];
    const float* w_hh1 = (const float*)d_in[5];
    const float* b1    = (const float*)d_in[6];
    float* out = (float*)d_out;

    float *pxT, *pgx, *pmid;
    cudaGetSymbolAddress((void**)&pxT,  g_xT);
    cudaGetSymbolAddress((void**)&pgx,  g_gx);
    cudaGetSymbolAddress((void**)&pmid, g_mid);

    const int SMEM = (100 * 132 + 100 * 68) * 4;   // 80000 B
    cudaFuncSetAttribute(gemm_tile8<100>, cudaFuncAttributeMaxDynamicSharedMemorySize, SMEM);
    cudaFuncSetAttribute(gemm_tile8<200>, cudaFuncAttributeMaxDynamicSharedMemorySize, SMEM);

    // x -> xT (T,B,IN)
    transpose_x<<<dim3(TT / 32, 4, BB), dim3(32, 8)>>>(x, pxT);

    // layer 0: gx = xT @ w_ih0^T + b0 ; scan -> g_mid
    gemm_tile8<100><<<dim3(TT * BB / 128, 7, 2), 256, SMEM>>>(pxT, w_ih0, b0, pgx);
    lstm_scan<<<128, 416>>>(pgx, w_hh0, pmid);

    // layer 1: gx = mid @ w_ih1^T + b1 (single K=200 launch, 2 chunks) ; scan -> out
    gemm_tile8<200><<<dim3(TT * BB / 128, 7, 2), 256, SMEM>>>(pmid, w_ih1, b1, pgx);
    lstm_scan<<<128, 416>>>(pgx, w_hh1, out);
}